// round 10
// baseline (speedup 1.0000x reference)
#include <cuda_runtime.h>
#include <cuda_fp16.h>
#include <cstdint>

#define HD 128
#define TILE_M 256
#define NTH 256
#define MAXT 8
#define MAXN 100000
#define XSTR_H 264                    // X row stride in halves (528 B), conflict-free ldsm
#define XROW_B 528
#define WSTR_H 72                     // W chunk row stride in halves (144 B)
#define WROW_B 144
#define WCH_B (128 * WSTR_H * 2)      // 18432 B per chunk
#define X_BYTES (TILE_M * XSTR_H * 2) // 135168
#define W_OFF X_BYTES
#define IDX_OFF (W_OFF + 2 * WCH_B)       // 172032
#define MB_OFF (IDX_OFF + 2 * TILE_M * 4) // 174080
#define SMEM_DYN (MB_OFF + 32)

// pre-transposed fp16 weights: [t][chunk][n=128][WSTR_H], 64 k per chunk
__device__ __align__(16) __half g_W1h[MAXT * 4 * 128 * WSTR_H];
__device__ __align__(16) __half g_W2h[MAXT * 2 * 128 * WSTR_H];
// fp16 copy of node_states (25.6 MB, L2-resident)
__device__ __align__(16) __half g_ns16[(size_t)MAXN * HD];

static __device__ __forceinline__ uint32_t s2u(const void* p) {
    uint32_t a;
    asm("{ .reg .u64 t; cvta.to.shared.u64 t, %1; cvt.u32.u64 %0, t; }" : "=r"(a) : "l"(p));
    return a;
}
static __device__ __forceinline__ void mma16(float* c, const uint32_t* a, uint32_t b0, uint32_t b1) {
    asm volatile(
        "mma.sync.aligned.m16n8k16.row.col.f32.f16.f16.f32 "
        "{%0,%1,%2,%3}, {%4,%5,%6,%7}, {%8,%9}, {%0,%1,%2,%3};"
        : "+f"(c[0]), "+f"(c[1]), "+f"(c[2]), "+f"(c[3])
        : "r"(a[0]), "r"(a[1]), "r"(a[2]), "r"(a[3]), "r"(b0), "r"(b1));
}
static __device__ __forceinline__ void ldsm4(uint32_t* r, uint32_t addr) {
    asm volatile("ldmatrix.sync.aligned.m8n8.x4.shared.b16 {%0,%1,%2,%3}, [%4];"
                 : "=r"(r[0]), "=r"(r[1]), "=r"(r[2]), "=r"(r[3]) : "r"(addr));
}
static __device__ __forceinline__ void mbar_init(uint32_t m, uint32_t cnt) {
    asm volatile("mbarrier.init.shared.b64 [%0], %1;" :: "r"(m), "r"(cnt) : "memory");
}
static __device__ __forceinline__ void mbar_expect(uint32_t m, uint32_t bytes) {
    asm volatile("mbarrier.arrive.expect_tx.shared.b64 _, [%0], %1;" :: "r"(m), "r"(bytes) : "memory");
}
static __device__ __forceinline__ void mbar_arrive(uint32_t m) {
    asm volatile("mbarrier.arrive.shared.b64 _, [%0];" :: "r"(m) : "memory");
}
static __device__ __forceinline__ void mbar_wait(uint32_t m, uint32_t parity) {
    asm volatile(
        "{\n\t.reg .pred P;\n\tW_%=:\n\t"
        "mbarrier.try_wait.parity.shared.b64 P, [%0], %1;\n\t"
        "@!P bra W_%=;\n\t}"
        :: "r"(m), "r"(parity) : "memory");
}
static __device__ __forceinline__ void bulk_ld(uint32_t dst, const void* src, uint32_t bytes, uint32_t mbar) {
    asm volatile("cp.async.bulk.shared::cta.global.mbarrier::complete_tx::bytes [%0], [%1], %2, [%3];"
                 :: "r"(dst), "l"(src), "r"(bytes), "r"(mbar) : "memory");
}
static __device__ __forceinline__ void red2(float* dst, float a, float b) {
    asm volatile("red.global.add.v2.f32 [%0], {%1,%2};" :: "l"(dst), "f"(a), "f"(b) : "memory");
}
static __device__ __forceinline__ void cpa16(uint32_t dst, const void* src) {
    asm volatile("cp.async.cg.shared.global [%0], [%1], 16;" :: "r"(dst), "l"(src) : "memory");
}
#define CPA_COMMIT() asm volatile("cp.async.commit_group;" ::: "memory")
template<int N> static __device__ __forceinline__ void cpa_wait() {
    asm volatile("cp.async.wait_group %0;" :: "n"(N) : "memory");
}

// ---------------- prep: zero output + fp16 node_states + transposed fp16 weights ----------------
__global__ void prep_all(const float* __restrict__ ns, const float* __restrict__ W1,
                         const float* __restrict__ W2, float4* __restrict__ out,
                         int N, int T, int n4) {
    int idx = blockIdx.x * blockDim.x + threadIdx.x;
    int stride = gridDim.x * blockDim.x;

    for (int i = idx; i < n4; i += stride) out[i] = make_float4(0.f, 0.f, 0.f, 0.f);

    int nns = N * (HD / 4);
    for (int i = idx; i < nns; i += stride) {
        float4 v = ((const float4*)ns)[i];
        uint2 w;
        __half2 a = __floats2half2_rn(v.x, v.y);
        __half2 b = __floats2half2_rn(v.z, v.w);
        w.x = *reinterpret_cast<uint32_t*>(&a);
        w.y = *reinterpret_cast<uint32_t*>(&b);
        *(uint2*)(g_ns16 + (size_t)i * 4) = w;
    }

    const int per_t1 = 4 * 128 * 64, per_t2 = 2 * 128 * 64;
    int tot1 = T * per_t1, tot2 = T * per_t2;
    for (int i = idx; i < tot1 + tot2; i += stride) {
        if (i < tot1) {
            int t = i / per_t1, r = i % per_t1;
            int c = r / (128 * 64), q = r % (128 * 64);
            int n = q / 64, kl = q % 64;
            float v = W1[(size_t)t * 256 * 128 + (size_t)(c * 64 + kl) * 128 + n];
            g_W1h[(((size_t)t * 4 + c) * 128 + n) * WSTR_H + kl] = __float2half_rn(v);
        } else {
            int j = i - tot1;
            int t = j / per_t2, r = j % per_t2;
            int c = r / (128 * 64), q = r % (128 * 64);
            int n = q / 64, kl = q % 64;
            float v = W2[(size_t)t * 128 * 128 + (size_t)(c * 64 + kl) * 128 + n];
            g_W2h[(((size_t)t * 2 + c) * 128 + n) * WSTR_H + kl] = __float2half_rn(v);
        }
    }
}

// one 64-k chunk, 64x64 warp tile: per k16-step 4 A + 4 B ldsm.x4, 32 mma
static __device__ __forceinline__ void gemm_chunk(float acc[4][8][4], uint32_t xa, uint32_t wb) {
    #pragma unroll
    for (int ks = 0; ks < 4; ks++) {
        uint32_t a[4][4], b[4][4];
        #pragma unroll
        for (int i = 0; i < 4; i++) ldsm4(a[i], xa + i * (16 * XROW_B) + ks * 32);
        #pragma unroll
        for (int p = 0; p < 4; p++) ldsm4(b[p], wb + p * (16 * WROW_B) + ks * 32);
        #pragma unroll
        for (int i = 0; i < 4; i++)
            #pragma unroll
            for (int j = 0; j < 8; j++)
                mma16(acc[i][j], a[i], b[j >> 1][(j & 1) * 2], b[j >> 1][(j & 1) * 2 + 1]);
    }
}

__global__ void __launch_bounds__(NTH, 1)
relmp_mma(const int* __restrict__ adj, float* __restrict__ out, int E) {
    extern __shared__ char raw[];
    __half* Xh = (__half*)raw;
    uint32_t Su = s2u(raw);
    const uint32_t Xu = Su;
    const uint32_t Wu = Su + W_OFF;
    int* s_src = (int*)(raw + IDX_OFF);
    int* s_tgt = s_src + TILE_M;
    const uint32_t mbF[2] = { Su + MB_OFF, Su + MB_OFF + 8 };
    const uint32_t mbE[2] = { Su + MB_OFF + 16, Su + MB_OFF + 24 };

    const int tid = threadIdx.x, warp = tid >> 5, lane = tid & 31;
    const int gid = lane >> 2, tig = lane & 3;
    const int wm = warp & 3, wn = warp >> 2;   // 4 (M) x 2 (N) warps, 64x64 tiles
    const int t = blockIdx.y, e0 = blockIdx.x * TILE_M;
    const int m_valid = min(TILE_M, E - e0);

    if (tid == 0) {
        mbar_init(mbF[0], 1); mbar_init(mbF[1], 1);
        mbar_init(mbE[0], 8); mbar_init(mbE[1], 8);
    }
    {
        int e = e0 + tid;
        int2 p = (e < E) ? ((const int2*)adj)[(size_t)t * E + e] : make_int2(0, 0);
        s_src[tid] = p.x; s_tgt[tid] = p.y;
    }
    __syncthreads();

    const __half* w1b = g_W1h + (size_t)t * 4 * 128 * WSTR_H;
    const __half* w2b = g_W2h + (size_t)t * 2 * 128 * WSTR_H;
    if (tid == 0) {
        mbar_expect(mbF[0], WCH_B); bulk_ld(Wu,         w1b,                WCH_B, mbF[0]);
        mbar_expect(mbF[1], WCH_B); bulk_ld(Wu + WCH_B, w1b + 128 * WSTR_H, WCH_B, mbF[1]);
    }

    // ---- async gather: 4 quarters, quarter q feeds GEMM1 chunk q ----
    {
        const int rl = lane >> 3;    // row within 4-row group
        const int cl = lane & 7;     // 16B slot within 128B quarter-row
        #pragma unroll
        for (int q = 0; q < 4; q++) {
            const int* list = (q < 2) ? s_src : s_tgt;
            #pragma unroll
            for (int it = 0; it < 8; it++) {
                int m = warp * 32 + it * 4 + rl;
                int node = list[m];
                const void* g = g_ns16 + (size_t)node * HD + (q & 1) * 64 + cl * 8;
                cpa16(Xu + (uint32_t)m * XROW_B + q * 128 + cl * 16, g);
            }
            CPA_COMMIT();
        }
    }

    // per-lane ldsm base offsets (bytes)
    const uint32_t arow = (uint32_t)(wm * 64 + (lane & 15)) * XROW_B + ((lane >> 4) & 1) * 16;
    const uint32_t brow = (uint32_t)(wn * 64 + ((lane & 7) + ((lane & 16) >> 1))) * WROW_B + ((lane & 8) << 1);

    int pf[2] = {0, 0}, pe[2] = {0, 0};

#define CONSUME(cidx, ccolbytes, ACC) do {                                           \
        const int b_ = (cidx) & 1;                                                   \
        mbar_wait(mbF[b_], pf[b_]); pf[b_] ^= 1;                                     \
        gemm_chunk(ACC, Xu + arow + (ccolbytes), Wu + b_ * WCH_B + brow);            \
        if (lane == 0) mbar_arrive(mbE[b_]);                                         \
        if (tid == 0 && (cidx) + 2 < 6) {                                            \
            mbar_wait(mbE[b_], pe[b_]); pe[b_] ^= 1;                                 \
            const __half* src_ = ((cidx) + 2 < 4) ? (w1b + ((cidx) + 2) * 128 * WSTR_H) \
                                                  : (w2b + ((cidx) - 2) * 128 * WSTR_H); \
            mbar_expect(mbF[b_], WCH_B);                                             \
            bulk_ld(Wu + b_ * WCH_B, src_, WCH_B, mbF[b_]);                          \
        }                                                                            \
    } while (0)

    float acc[4][8][4];
    #pragma unroll
    for (int i = 0; i < 4; i++)
        #pragma unroll
        for (int j = 0; j < 8; j++)
            #pragma unroll
            for (int q = 0; q < 4; q++) acc[i][j][q] = 0.f;

    // GEMM1: K=256; drain gather quarter c, then consume chunk c
    cpa_wait<3>(); __syncthreads(); CONSUME(0, 0,   acc);
    cpa_wait<2>(); __syncthreads(); CONSUME(1, 128, acc);
    cpa_wait<1>(); __syncthreads(); CONSUME(2, 256, acc);
    cpa_wait<0>(); __syncthreads(); CONSUME(3, 384, acc);

    // epilogue1: H = relu(acc) -> fp16 into X cols 0..127
    // (safe without extra barrier: slowest warp still in chunk3 reads X bytes
    //  [384,512) per row; epi1 writes bytes [0,256) -- disjoint)
    #pragma unroll
    for (int i = 0; i < 4; i++) {
        int r0 = wm * 64 + i * 16 + gid;
        #pragma unroll
        for (int j = 0; j < 8; j++) {
            int cn = wn * 64 + j * 8 + tig * 2;
            __half2 lo = __floats2half2_rn(fmaxf(acc[i][j][0], 0.f), fmaxf(acc[i][j][1], 0.f));
            __half2 hi = __floats2half2_rn(fmaxf(acc[i][j][2], 0.f), fmaxf(acc[i][j][3], 0.f));
            *(__half2*)(Xh + (size_t)r0 * XSTR_H + cn)       = lo;
            *(__half2*)(Xh + (size_t)(r0 + 8) * XSTR_H + cn) = hi;
        }
    }
    __syncthreads();

    // GEMM2: K=128 (chunks 4..5 = W2)
    float acc2[4][8][4];
    #pragma unroll
    for (int i = 0; i < 4; i++)
        #pragma unroll
        for (int j = 0; j < 8; j++)
            #pragma unroll
            for (int q = 0; q < 4; q++) acc2[i][j][q] = 0.f;

    CONSUME(4, 0,   acc2);
    CONSUME(5, 128, acc2);

    // fused epilogue2 + scatter: relu + red.global.add.v2 straight from registers
    #pragma unroll
    for (int i = 0; i < 4; i++) {
        int r0 = wm * 64 + i * 16 + gid;
        int r1 = r0 + 8;
        int n0 = s_tgt[r0], n1 = s_tgt[r1];
        float* d0 = out + (size_t)n0 * HD + wn * 64 + tig * 2;
        float* d1 = out + (size_t)n1 * HD + wn * 64 + tig * 2;
        bool v0 = (r0 < m_valid), v1 = (r1 < m_valid);
        #pragma unroll
        for (int j = 0; j < 8; j++) {
            if (v0) red2(d0 + j * 8, fmaxf(acc2[i][j][0], 0.f), fmaxf(acc2[i][j][1], 0.f));
            if (v1) red2(d1 + j * 8, fmaxf(acc2[i][j][2], 0.f), fmaxf(acc2[i][j][3], 0.f));
        }
    }
#undef CONSUME
}

extern "C" void kernel_launch(void* const* d_in, const int* in_sizes, int n_in,
                              void* d_out, int out_size) {
    const float* node_states = (const float*)d_in[0];
    const int*   adj         = (const int*)d_in[1];
    const float* W1          = (const float*)d_in[2];
    const float* W2          = (const float*)d_in[3];
    float*       out         = (float*)d_out;

    const int T = in_sizes[3] / (HD * HD);
    const int E = in_sizes[1] / (T * 2);
    const int N = in_sizes[0] / HD;

    int n4 = out_size / 4;
    int work = n4;
    int nns = N * (HD / 4);
    if (nns > work) work = nns;
    prep_all<<<(work + 255) / 256, 256>>>(node_states, W1, W2, (float4*)out, N, T, n4);

    const int tiles = (E + TILE_M - 1) / TILE_M;
    cudaFuncSetAttribute(relmp_mma, cudaFuncAttributeMaxDynamicSharedMemorySize, SMEM_DYN);
    relmp_mma<<<dim3(tiles, T), NTH, SMEM_DYN>>>(adj, out, E);
}

// round 11
// speedup vs baseline: 1.2570x; 1.2570x over previous
#include <cuda_runtime.h>
#include <cuda_fp16.h>
#include <cstdint>

#define HD 128
#define TILE_M 128
#define NTH 256
#define MAXT 8
#define MAXN 100000
#define XSTR_H 264                    // X row stride in halves (528 B), conflict-free ldsm
#define XROW_B 528
#define WSTR_H 72                     // W chunk row stride in halves (144 B)
#define WROW_B 144
#define WCH_B (128 * WSTR_H * 2)      // 18432 B per chunk
#define X_BYTES (TILE_M * XSTR_H * 2) // 67584
#define W_OFF X_BYTES
#define IDX_OFF (W_OFF + 2 * WCH_B)       // 104448
#define MB_OFF (IDX_OFF + 2 * TILE_M * 4) // 105472
#define SMEM_DYN (MB_OFF + 32)

// pre-transposed fp16 weights: [t][chunk][n=128][WSTR_H], 64 k per chunk
__device__ __align__(16) __half g_W1h[MAXT * 4 * 128 * WSTR_H];
__device__ __align__(16) __half g_W2h[MAXT * 2 * 128 * WSTR_H];
// fp16 copy of node_states (25.6 MB, L2-resident)
__device__ __align__(16) __half g_ns16[(size_t)MAXN * HD];

static __device__ __forceinline__ uint32_t s2u(const void* p) {
    uint32_t a;
    asm("{ .reg .u64 t; cvta.to.shared.u64 t, %1; cvt.u32.u64 %0, t; }" : "=r"(a) : "l"(p));
    return a;
}
static __device__ __forceinline__ void mma16(float* c, const uint32_t* a, uint32_t b0, uint32_t b1) {
    asm volatile(
        "mma.sync.aligned.m16n8k16.row.col.f32.f16.f16.f32 "
        "{%0,%1,%2,%3}, {%4,%5,%6,%7}, {%8,%9}, {%0,%1,%2,%3};"
        : "+f"(c[0]), "+f"(c[1]), "+f"(c[2]), "+f"(c[3])
        : "r"(a[0]), "r"(a[1]), "r"(a[2]), "r"(a[3]), "r"(b0), "r"(b1));
}
static __device__ __forceinline__ void ldsm4(uint32_t* r, uint32_t addr) {
    asm volatile("ldmatrix.sync.aligned.m8n8.x4.shared.b16 {%0,%1,%2,%3}, [%4];"
                 : "=r"(r[0]), "=r"(r[1]), "=r"(r[2]), "=r"(r[3]) : "r"(addr));
}
static __device__ __forceinline__ void mbar_init(uint32_t m, uint32_t cnt) {
    asm volatile("mbarrier.init.shared.b64 [%0], %1;" :: "r"(m), "r"(cnt) : "memory");
}
static __device__ __forceinline__ void mbar_expect(uint32_t m, uint32_t bytes) {
    asm volatile("mbarrier.arrive.expect_tx.shared.b64 _, [%0], %1;" :: "r"(m), "r"(bytes) : "memory");
}
static __device__ __forceinline__ void mbar_arrive(uint32_t m) {
    asm volatile("mbarrier.arrive.shared.b64 _, [%0];" :: "r"(m) : "memory");
}
static __device__ __forceinline__ void mbar_wait(uint32_t m, uint32_t parity) {
    asm volatile(
        "{\n\t.reg .pred P;\n\tW_%=:\n\t"
        "mbarrier.try_wait.parity.shared.b64 P, [%0], %1;\n\t"
        "@!P bra W_%=;\n\t}"
        :: "r"(m), "r"(parity) : "memory");
}
static __device__ __forceinline__ void bulk_ld(uint32_t dst, const void* src, uint32_t bytes, uint32_t mbar) {
    asm volatile("cp.async.bulk.shared::cta.global.mbarrier::complete_tx::bytes [%0], [%1], %2, [%3];"
                 :: "r"(dst), "l"(src), "r"(bytes), "r"(mbar) : "memory");
}
static __device__ __forceinline__ void red2(float* dst, float a, float b) {
    asm volatile("red.global.add.v2.f32 [%0], {%1,%2};" :: "l"(dst), "f"(a), "f"(b) : "memory");
}
static __device__ __forceinline__ void cpa16(uint32_t dst, const void* src) {
    asm volatile("cp.async.cg.shared.global [%0], [%1], 16;" :: "r"(dst), "l"(src) : "memory");
}
#define CPA_COMMIT() asm volatile("cp.async.commit_group;" ::: "memory")
template<int N> static __device__ __forceinline__ void cpa_wait() {
    asm volatile("cp.async.wait_group %0;" :: "n"(N) : "memory");
}

// ---------------- prep: zero output + fp16 node_states + transposed fp16 weights ----------------
__global__ void prep_all(const float* __restrict__ ns, const float* __restrict__ W1,
                         const float* __restrict__ W2, float4* __restrict__ out,
                         int N, int T, int n4) {
    int idx = blockIdx.x * blockDim.x + threadIdx.x;
    int stride = gridDim.x * blockDim.x;

    for (int i = idx; i < n4; i += stride) out[i] = make_float4(0.f, 0.f, 0.f, 0.f);

    int nns = N * (HD / 4);
    for (int i = idx; i < nns; i += stride) {
        float4 v = ((const float4*)ns)[i];
        uint2 w;
        __half2 a = __floats2half2_rn(v.x, v.y);
        __half2 b = __floats2half2_rn(v.z, v.w);
        w.x = *reinterpret_cast<uint32_t*>(&a);
        w.y = *reinterpret_cast<uint32_t*>(&b);
        *(uint2*)(g_ns16 + (size_t)i * 4) = w;
    }

    const int per_t1 = 4 * 128 * 64, per_t2 = 2 * 128 * 64;
    int tot1 = T * per_t1, tot2 = T * per_t2;
    for (int i = idx; i < tot1 + tot2; i += stride) {
        if (i < tot1) {
            int t = i / per_t1, r = i % per_t1;
            int c = r / (128 * 64), q = r % (128 * 64);
            int n = q / 64, kl = q % 64;
            float v = W1[(size_t)t * 256 * 128 + (size_t)(c * 64 + kl) * 128 + n];
            g_W1h[(((size_t)t * 4 + c) * 128 + n) * WSTR_H + kl] = __float2half_rn(v);
        } else {
            int j = i - tot1;
            int t = j / per_t2, r = j % per_t2;
            int c = r / (128 * 64), q = r % (128 * 64);
            int n = q / 64, kl = q % 64;
            float v = W2[(size_t)t * 128 * 128 + (size_t)(c * 64 + kl) * 128 + n];
            g_W2h[(((size_t)t * 2 + c) * 128 + n) * WSTR_H + kl] = __float2half_rn(v);
        }
    }
}

// one 64-k chunk: 4 k16-steps; per step: 2 A ldsm.x4 + 4 B ldsm.x4 + 16 mma
static __device__ __forceinline__ void gemm_chunk(float acc[2][8][4], uint32_t xa, uint32_t wb) {
    #pragma unroll
    for (int ks = 0; ks < 4; ks++) {
        uint32_t a0[4], a1[4], b[4][4];
        ldsm4(a0, xa + ks * 32);
        ldsm4(a1, xa + 16 * XROW_B + ks * 32);
        #pragma unroll
        for (int p = 0; p < 4; p++) ldsm4(b[p], wb + p * (16 * WROW_B) + ks * 32);
        #pragma unroll
        for (int j = 0; j < 8; j++) {
            mma16(acc[0][j], a0, b[j >> 1][(j & 1) * 2], b[j >> 1][(j & 1) * 2 + 1]);
            mma16(acc[1][j], a1, b[j >> 1][(j & 1) * 2], b[j >> 1][(j & 1) * 2 + 1]);
        }
    }
}

__global__ void __launch_bounds__(NTH, 2)
relmp_mma(const int* __restrict__ adj, float* __restrict__ out, int E) {
    extern __shared__ char raw[];
    __half* Xh = (__half*)raw;
    uint32_t Su = s2u(raw);
    const uint32_t Xu = Su;
    const uint32_t Wu = Su + W_OFF;
    int* s_src = (int*)(raw + IDX_OFF);
    int* s_tgt = s_src + TILE_M;
    const uint32_t mbF[2] = { Su + MB_OFF, Su + MB_OFF + 8 };
    const uint32_t mbE[2] = { Su + MB_OFF + 16, Su + MB_OFF + 24 };

    const int tid = threadIdx.x, warp = tid >> 5, lane = tid & 31;
    const int gid = lane >> 2, tig = lane & 3;
    const int wm = warp & 3, wn = warp >> 2;
    const int t = blockIdx.y, e0 = blockIdx.x * TILE_M;
    const int m_valid = min(TILE_M, E - e0);

    if (tid == 0) {
        mbar_init(mbF[0], 1); mbar_init(mbF[1], 1);
        mbar_init(mbE[0], 8); mbar_init(mbE[1], 8);   // one arrive per warp
    }
    if (tid < TILE_M) {
        int e = e0 + tid;
        int2 p = (e < E) ? ((const int2*)adj)[(size_t)t * E + e] : make_int2(0, 0);
        s_src[tid] = p.x; s_tgt[tid] = p.y;
    }
    __syncthreads();

    const __half* w1b = g_W1h + (size_t)t * 4 * 128 * WSTR_H;
    const __half* w2b = g_W2h + (size_t)t * 2 * 128 * WSTR_H;
    if (tid == 0) {
        mbar_expect(mbF[0], WCH_B); bulk_ld(Wu,         w1b,                WCH_B, mbF[0]);
        mbar_expect(mbF[1], WCH_B); bulk_ld(Wu + WCH_B, w1b + 128 * WSTR_H, WCH_B, mbF[1]);
    }

    // ---- async gather: group 0 = src half (X cols 0..127), group 1 = tgt half ----
    {
        const int hl = lane >> 4;     // row within pair
        const int l16 = lane & 15;    // 16B slot within 256B half-row
        #pragma unroll
        for (int it = 0; it < 8; it++) {
            int m = warp * 16 + it * 2 + hl;
            int node = s_src[m];
            cpa16(Xu + (uint32_t)m * XROW_B + l16 * 16,
                  g_ns16 + (size_t)node * HD + l16 * 8);
        }
        CPA_COMMIT();
        #pragma unroll
        for (int it = 0; it < 8; it++) {
            int m = warp * 16 + it * 2 + hl;
            int node = s_tgt[m];
            cpa16(Xu + (uint32_t)m * XROW_B + 256 + l16 * 16,
                  g_ns16 + (size_t)node * HD + l16 * 8);
        }
        CPA_COMMIT();
    }

    // per-lane ldsm base offsets (bytes)
    const uint32_t arow = (uint32_t)(wm * 32 + (lane & 15)) * XROW_B + ((lane >> 4) & 1) * 16;
    const uint32_t brow = (uint32_t)(wn * 64 + ((lane & 7) + ((lane & 16) >> 1))) * WROW_B + ((lane & 8) << 1);

    int pf[2] = {0, 0}, pe[2] = {0, 0};

#define CONSUME(cidx, ccolbytes, ACC) do {                                           \
        const int b_ = (cidx) & 1;                                                   \
        mbar_wait(mbF[b_], pf[b_]); pf[b_] ^= 1;                                     \
        gemm_chunk(ACC, Xu + arow + (ccolbytes), Wu + b_ * WCH_B + brow);            \
        if (lane == 0) mbar_arrive(mbE[b_]);                                         \
        if (tid == 0 && (cidx) + 2 < 6) {                                            \
            mbar_wait(mbE[b_], pe[b_]); pe[b_] ^= 1;                                 \
            const __half* src_ = ((cidx) + 2 < 4) ? (w1b + ((cidx) + 2) * 128 * WSTR_H) \
                                                  : (w2b + ((cidx) - 2) * 128 * WSTR_H); \
            mbar_expect(mbF[b_], WCH_B);                                             \
            bulk_ld(Wu + b_ * WCH_B, src_, WCH_B, mbF[b_]);                          \
        }                                                                            \
    } while (0)

    float acc[2][8][4];
    #pragma unroll
    for (int i = 0; i < 2; i++)
        #pragma unroll
        for (int j = 0; j < 8; j++)
            #pragma unroll
            for (int q = 0; q < 4; q++) acc[i][j][q] = 0.f;

    // GEMM1: K=256; src chunks while tgt gather is still in flight
    cpa_wait<1>();
    __syncthreads();
    CONSUME(0, 0,   acc);
    CONSUME(1, 128, acc);
    cpa_wait<0>();
    __syncthreads();
    CONSUME(2, 256, acc);
    CONSUME(3, 384, acc);

    // epilogue1 without barrier: laggiest warp reads X bytes [256,512),
    // epi1 writes bytes [0,256) -- disjoint (warp skew bounded by mbF gating)
    #pragma unroll
    for (int i = 0; i < 2; i++) {
        int r0 = wm * 32 + i * 16 + gid;
        #pragma unroll
        for (int j = 0; j < 8; j++) {
            int cn = wn * 64 + j * 8 + tig * 2;
            __half2 lo = __floats2half2_rn(fmaxf(acc[i][j][0], 0.f), fmaxf(acc[i][j][1], 0.f));
            __half2 hi = __floats2half2_rn(fmaxf(acc[i][j][2], 0.f), fmaxf(acc[i][j][3], 0.f));
            *(__half2*)(Xh + (size_t)r0 * XSTR_H + cn)       = lo;
            *(__half2*)(Xh + (size_t)(r0 + 8) * XSTR_H + cn) = hi;
        }
    }
    __syncthreads();

    // GEMM2: K=128, chunks 4..5
    float acc2[2][8][4];
    #pragma unroll
    for (int i = 0; i < 2; i++)
        #pragma unroll
        for (int j = 0; j < 8; j++)
            #pragma unroll
            for (int q = 0; q < 4; q++) acc2[i][j][q] = 0.f;

    CONSUME(4, 0,   acc2);
    CONSUME(5, 128, acc2);

    // fused epilogue2 + scatter: relu + red.global.add.v2 straight from registers
    #pragma unroll
    for (int i = 0; i < 2; i++) {
        int r0 = wm * 32 + i * 16 + gid;
        int r1 = r0 + 8;
        int n0 = s_tgt[r0], n1 = s_tgt[r1];
        float* d0 = out + (size_t)n0 * HD + wn * 64 + tig * 2;
        float* d1 = out + (size_t)n1 * HD + wn * 64 + tig * 2;
        bool v0 = (r0 < m_valid), v1 = (r1 < m_valid);
        #pragma unroll
        for (int j = 0; j < 8; j++) {
            if (v0) red2(d0 + j * 8, fmaxf(acc2[i][j][0], 0.f), fmaxf(acc2[i][j][1], 0.f));
            if (v1) red2(d1 + j * 8, fmaxf(acc2[i][j][2], 0.f), fmaxf(acc2[i][j][3], 0.f));
        }
    }
#undef CONSUME
}

extern "C" void kernel_launch(void* const* d_in, const int* in_sizes, int n_in,
                              void* d_out, int out_size) {
    const float* node_states = (const float*)d_in[0];
    const int*   adj         = (const int*)d_in[1];
    const float* W1          = (const float*)d_in[2];
    const float* W2          = (const float*)d_in[3];
    float*       out         = (float*)d_out;

    const int T = in_sizes[3] / (HD * HD);
    const int E = in_sizes[1] / (T * 2);
    const int N = in_sizes[0] / HD;

    int n4 = out_size / 4;
    int work = n4;
    int nns = N * (HD / 4);
    if (nns > work) work = nns;
    prep_all<<<(work + 255) / 256, 256>>>(node_states, W1, W2, (float4*)out, N, T, n4);

    const int tiles = (E + TILE_M - 1) / TILE_M;
    cudaFuncSetAttribute(relmp_mma, cudaFuncAttributeMaxDynamicSharedMemorySize, SMEM_DYN);
    relmp_mma<<<dim3(tiles, T), NTH, SMEM_DYN>>>(adj, out, E);
}